// round 9
// baseline (speedup 1.0000x reference)
#include <cuda_runtime.h>
#include <stdint.h>
#include <stdlib.h>

#define NMAX 80000
#define EMAX 1280000
#define HD   64
#define OD   10
#define GB   512
#define SCB  256                      // scan block size
#define NSB  ((NMAX + SCB - 1) / SCB) // 313 scan blocks

// Scratch (module globals; eager-loaded in ctor)
__device__ int    g_degi[NMAX];        // in-degree (no self loop)
__device__ int    g_rowptr[NMAX + 1];  // CSR row pointers (by dst)
__device__ int    g_cursor[NMAX];      // fill cursors
__device__ int    g_csrc[EMAX];        // CSR column (source node) array
__device__ int    g_tmp[NMAX];         // scan temp (inclusive per-block)
__device__ int    g_bsum[NSB + 1];     // per-block sums -> exclusive offsets
__device__ float  g_dinv[NMAX];
__device__ float4 g_A4[NMAX * 16];     // ts = (X @ W) * dinv[row]
__device__ float4 g_B4[NMAX * 16];     // layer output h
__device__ float4 g_S4[GB * 16];       // pooled sums
__device__ float  g_cnt[GB];

// ---------------------------------------------------------------------------
__global__ void k_init(int n) {
    int i = blockIdx.x * blockDim.x + threadIdx.x;
    if (i < n) g_degi[i] = 0;
    if (i < GB * 16) g_S4[i] = make_float4(0.f, 0.f, 0.f, 0.f);
    if (i < GB) g_cnt[i] = 0.0f;
}

__global__ void k_hist(const int* __restrict__ dst, int e) {
    int i = blockIdx.x * blockDim.x + threadIdx.x;
    if (i < e) atomicAdd(&g_degi[dst[i]], 1);
}

// per-block inclusive scan of g_degi -> g_tmp, block sums -> g_bsum
__global__ void k_scan1(int n) {
    __shared__ int sh[SCB];
    int i = blockIdx.x * SCB + threadIdx.x;
    int v = (i < n) ? g_degi[i] : 0;
    sh[threadIdx.x] = v;
    __syncthreads();
#pragma unroll
    for (int off = 1; off < SCB; off <<= 1) {
        int t = (threadIdx.x >= off) ? sh[threadIdx.x - off] : 0;
        __syncthreads();
        sh[threadIdx.x] += t;
        __syncthreads();
    }
    if (i < n) g_tmp[i] = sh[threadIdx.x];
    if (threadIdx.x == SCB - 1) g_bsum[blockIdx.x] = sh[SCB - 1];
}

// single-block exclusive scan of g_bsum (NSB entries), 512 threads
__global__ void k_scan2(int nb) {
    __shared__ int sh[512];
    int v = (threadIdx.x < nb) ? g_bsum[threadIdx.x] : 0;
    sh[threadIdx.x] = v;
    __syncthreads();
#pragma unroll
    for (int off = 1; off < 512; off <<= 1) {
        int t = (threadIdx.x >= off) ? sh[threadIdx.x - off] : 0;
        __syncthreads();
        sh[threadIdx.x] += t;
        __syncthreads();
    }
    if (threadIdx.x < nb) g_bsum[threadIdx.x] = sh[threadIdx.x] - v;  // exclusive
}

// rowptr[i] = exclusive prefix; cursor[i] = rowptr[i]; dinv from degree
__global__ void k_scan3(int n, int e) {
    int i = blockIdx.x * blockDim.x + threadIdx.x;
    if (i < n) {
        int excl = g_tmp[i] - g_degi[i] + g_bsum[i / SCB];
        g_rowptr[i] = excl;
        g_cursor[i] = excl;
        g_dinv[i]   = rsqrtf((float)(g_degi[i] + 1));
    }
    if (i == 0) g_rowptr[n] = e;
}

__global__ void k_fill(const int* __restrict__ src,
                       const int* __restrict__ dst, int e) {
    int i = blockIdx.x * blockDim.x + threadIdx.x;
    if (i >= e) return;
    int d = dst[i];
    int pos = atomicAdd(&g_cursor[d], 1);
    g_csrc[pos] = src[i];
}

// ---------------------------------------------------------------------------
// per-warp row GEMM: A[row] = (X[row] @ W) * dinv[row]
__global__ void k_gemm_scale(const float* __restrict__ X,
                             const float* __restrict__ W,
                             int n) {
    __shared__ float Ws[HD * HD];
    for (int i = threadIdx.x; i < HD * HD; i += blockDim.x)
        Ws[i] = W[i];
    __syncthreads();

    int warp = threadIdx.x >> 5;
    int lane = threadIdx.x & 31;
    int row  = blockIdx.x * (blockDim.x >> 5) + warp;
    if (row >= n) return;

    float x0 = X[row * HD + lane];
    float x1 = X[row * HD + lane + 32];
    float a0 = 0.f, a1 = 0.f;
#pragma unroll
    for (int k = 0; k < HD; k++) {
        float xk = __shfl_sync(0xffffffffu, (k < 32) ? x0 : x1, k & 31);
        a0 = fmaf(xk, Ws[k * HD + lane], a0);
        a1 = fmaf(xk, Ws[k * HD + lane + 32], a1);
    }
    float s = g_dinv[row];
    float* A = (float*)g_A4;
    A[row * HD + lane]      = a0 * s;
    A[row * HD + lane + 32] = a1 * s;
}

// ---------------------------------------------------------------------------
// Cooperative gather core: 16 lanes per node. Lanes load 16 edge indices in
// one coalesced LDG, broadcast via shfl(width=16), then issue up to 16
// INDEPENDENT float4 row loads -> high MLP instead of per-edge dep chains.
__device__ __forceinline__ float4 gather_node(int node, int sub) {
    float4 acc = g_A4[node * 16 + sub];          // self-loop seed
    int beg = __ldg(&g_rowptr[node]);
    int end = __ldg(&g_rowptr[node + 1]);

    for (int base = beg; base < end; base += 16) {
        int j = base + sub;
        int myidx = (j < end) ? __ldg(&g_csrc[j]) : -1;
        int cnt = end - base; if (cnt > 16) cnt = 16;
#pragma unroll 16
        for (int t = 0; t < 16; t++) {
            if (t >= cnt) break;
            int s = __shfl_sync(0xffffffffu, myidx, t, 16);
            float4 v = __ldg(&g_A4[s * 16 + sub]);
            acc.x += v.x; acc.y += v.y; acc.z += v.z; acc.w += v.w;
        }
    }
    return acc;
}

// gather layer 1: h1 = relu(dinv*(selfA + sum_nb A) + b) -> g_B4
__global__ void k_gather_store(const float* __restrict__ bias, int n) {
    int gid  = blockIdx.x * blockDim.x + threadIdx.x;
    int node = gid >> 4;
    int sub  = gid & 15;
    if (node >= n) return;

    float4 acc = gather_node(node, sub);
    float d = g_dinv[node];
    float4 b = __ldg(&((const float4*)bias)[sub]);
    acc.x = fmaxf(fmaf(acc.x, d, b.x), 0.f);
    acc.y = fmaxf(fmaf(acc.y, d, b.y), 0.f);
    acc.z = fmaxf(fmaf(acc.z, d, b.z), 0.f);
    acc.w = fmaxf(fmaf(acc.w, d, b.w), 0.f);
    g_B4[node * 16 + sub] = acc;
}

// gather layer 2 fused with pooling: h2 never hits memory
__global__ void k_gather_pool(const float* __restrict__ bias,
                              const int* __restrict__ batch, int n) {
    int gid  = blockIdx.x * blockDim.x + threadIdx.x;
    int node = gid >> 4;
    int sub  = gid & 15;
    if (node >= n) return;

    float4 acc = gather_node(node, sub);
    float d = g_dinv[node];
    float4 b = __ldg(&((const float4*)bias)[sub]);
    acc.x = fmaxf(fmaf(acc.x, d, b.x), 0.f);
    acc.y = fmaxf(fmaf(acc.y, d, b.y), 0.f);
    acc.z = fmaxf(fmaf(acc.z, d, b.z), 0.f);
    acc.w = fmaxf(fmaf(acc.w, d, b.w), 0.f);

    int g = __ldg(&batch[node]);
    float4* p = &g_S4[g * 16 + sub];
    asm volatile("red.global.add.v4.f32 [%0], {%1,%2,%3,%4};"
                 :: "l"(p), "f"(acc.x), "f"(acc.y), "f"(acc.z), "f"(acc.w)
                 : "memory");
    if (sub == 0) atomicAdd(&g_cnt[g], 1.0f);
}

// ---------------------------------------------------------------------------
__global__ void k_head(const float* __restrict__ Wfc,
                       const float* __restrict__ bfc,
                       float* __restrict__ out) {
    __shared__ float Wf[HD * OD];
    __shared__ float bf[OD];
    for (int i = threadIdx.x; i < HD * OD; i += blockDim.x) Wf[i] = Wfc[i];
    if (threadIdx.x < OD) bf[threadIdx.x] = bfc[threadIdx.x];
    __syncthreads();

    int g = blockIdx.x * blockDim.x + threadIdx.x;
    if (g >= GB) return;

    const float* sums = (const float*)g_S4;
    float inv = 1.0f / fmaxf(g_cnt[g], 1.0f);
    float logits[OD];
#pragma unroll
    for (int o = 0; o < OD; o++) logits[o] = bf[o];
#pragma unroll 8
    for (int h = 0; h < HD; h++) {
        float p = sums[g * HD + h] * inv;
#pragma unroll
        for (int o = 0; o < OD; o++)
            logits[o] = fmaf(p, Wf[h * OD + o], logits[o]);
    }
    float m = logits[0];
#pragma unroll
    for (int o = 1; o < OD; o++) m = fmaxf(m, logits[o]);
    float sum = 0.f;
#pragma unroll
    for (int o = 0; o < OD; o++) sum += __expf(logits[o] - m);
    float lse = __logf(sum);
#pragma unroll
    for (int o = 0; o < OD; o++) out[g * OD + o] = logits[o] - m - lse;
}

// ---------------------------------------------------------------------------
static float* s_dB = nullptr;

namespace {
struct ModulePreload {
    ModulePreload() {
        setenv("CUDA_MODULE_LOADING", "EAGER", 1);
        cudaFree(0);
        void* p = nullptr;
        cudaGetSymbolAddress(&p, g_B4);
        s_dB = (float*)p;
        cudaFuncAttributes a;
        cudaFuncGetAttributes(&a, (const void*)k_init);
        cudaFuncGetAttributes(&a, (const void*)k_hist);
        cudaFuncGetAttributes(&a, (const void*)k_scan1);
        cudaFuncGetAttributes(&a, (const void*)k_scan2);
        cudaFuncGetAttributes(&a, (const void*)k_scan3);
        cudaFuncGetAttributes(&a, (const void*)k_fill);
        cudaFuncGetAttributes(&a, (const void*)k_gemm_scale);
        cudaFuncGetAttributes(&a, (const void*)k_gather_store);
        cudaFuncGetAttributes(&a, (const void*)k_gather_pool);
        cudaFuncGetAttributes(&a, (const void*)k_head);
        k_init<<<1, 32>>>(0);
        k_hist<<<1, 32>>>((const int*)s_dB, 0);
        k_scan1<<<1, SCB>>>(0);
        k_scan2<<<1, 512>>>(0);
        k_scan3<<<1, 32>>>(0, 0);
        k_fill<<<1, 32>>>((const int*)s_dB, (const int*)s_dB, 0);
        k_gemm_scale<<<1, 256>>>(s_dB, s_dB, 0);
        k_gather_store<<<1, 32>>>(s_dB, 0);
        k_gather_pool<<<1, 32>>>(s_dB, (const int*)s_dB, 0);
        cudaDeviceSynchronize();   // host code outside kernel_launch: allowed
    }
};
static ModulePreload s_preload;
}

// ---------------------------------------------------------------------------
extern "C" void kernel_launch(void* const* d_in, const int* in_sizes, int n_in,
                              void* d_out, int out_size) {
    const float* x    = (const float*)d_in[0];
    const int*   ei   = (const int*)d_in[1];
    const int*   bat  = (const int*)d_in[2];
    const float* W1   = (const float*)d_in[3];
    const float* b1   = (const float*)d_in[4];
    const float* W2   = (const float*)d_in[5];
    const float* b2   = (const float*)d_in[6];
    const float* Wfc  = (const float*)d_in[7];
    const float* bfc  = (const float*)d_in[8];
    float*       out  = (float*)d_out;

    const int n = in_sizes[0] / HD;       // 80000
    const int e = in_sizes[1] / 2;        // 1280000
    const int* src = ei;
    const int* dst = ei + e;

    const int T = 256;
    int nB  = (n + T - 1) / T;
    int eB  = (e + T - 1) / T;
    int n16 = (n * 16 + T - 1) / T;
    int gemmB = (n + 7) / 8;

    // CSR build (by dst) + dinv
    k_init<<<nB, T>>>(n);
    k_hist<<<eB, T>>>(dst, e);
    k_scan1<<<(n + SCB - 1) / SCB, SCB>>>(n);
    k_scan2<<<1, 512>>>((n + SCB - 1) / SCB);
    k_scan3<<<nB, T>>>(n, e);
    k_fill<<<eB, T>>>(src, dst, e);

    // layer 1
    k_gemm_scale<<<gemmB, T>>>(x, W1, n);
    k_gather_store<<<n16, T>>>(b1, n);
    // layer 2 (+ fused pooling)
    k_gemm_scale<<<gemmB, T>>>(s_dB, W2, n);
    k_gather_pool<<<n16, T>>>(b2, bat, n);
    // head
    k_head<<<1, GB>>>(Wfc, bfc, out);
}

// round 10
// speedup vs baseline: 1.1798x; 1.1798x over previous
#include <cuda_runtime.h>
#include <stdint.h>
#include <stdlib.h>

#define NMAX 80000
#define EMAX 1280000
#define HD   64
#define OD   10
#define GB   512
#define SCB  256                      // scan block size
#define NSB  ((NMAX + SCB - 1) / SCB) // 313 scan blocks

// Scratch (module globals; eager-loaded in ctor)
__device__ int    g_degi[NMAX];        // in-degree (no self loop)
__device__ int    g_rowptr[NMAX + 1];  // CSR row pointers (by dst)
__device__ int    g_cursor[NMAX];      // fill cursors
__device__ int    g_csrc[EMAX];        // CSR column (source node) array
__device__ int    g_tmp[NMAX];         // scan temp (inclusive per-block)
__device__ int    g_bsum[NSB + 1];     // per-block sums -> exclusive offsets
__device__ float  g_dinv[NMAX];
__device__ float4 g_A4[NMAX * 16];     // ts = (X @ W) * dinv[row]
__device__ float4 g_B4[NMAX * 16];     // layer output h
__device__ float4 g_S4[GB * 16];       // pooled sums
__device__ float  g_cnt[GB];

// ---------------------------------------------------------------------------
__global__ void k_init(int n) {
    int i = blockIdx.x * blockDim.x + threadIdx.x;
    if (i < n) g_degi[i] = 0;
    if (i < GB * 16) g_S4[i] = make_float4(0.f, 0.f, 0.f, 0.f);
    if (i < GB) g_cnt[i] = 0.0f;
}

__global__ void k_hist(const int* __restrict__ dst, int e) {
    int i = blockIdx.x * blockDim.x + threadIdx.x;
    if (i < e) atomicAdd(&g_degi[dst[i]], 1);
}

// per-block inclusive scan of g_degi -> g_tmp, block sums -> g_bsum
__global__ void k_scan1(int n) {
    __shared__ int sh[SCB];
    int i = blockIdx.x * SCB + threadIdx.x;
    int v = (i < n) ? g_degi[i] : 0;
    sh[threadIdx.x] = v;
    __syncthreads();
#pragma unroll
    for (int off = 1; off < SCB; off <<= 1) {
        int t = (threadIdx.x >= off) ? sh[threadIdx.x - off] : 0;
        __syncthreads();
        sh[threadIdx.x] += t;
        __syncthreads();
    }
    if (i < n) g_tmp[i] = sh[threadIdx.x];
    if (threadIdx.x == SCB - 1) g_bsum[blockIdx.x] = sh[SCB - 1];
}

// single-block exclusive scan of g_bsum (NSB entries), 512 threads
__global__ void k_scan2(int nb) {
    __shared__ int sh[512];
    int v = (threadIdx.x < nb) ? g_bsum[threadIdx.x] : 0;
    sh[threadIdx.x] = v;
    __syncthreads();
#pragma unroll
    for (int off = 1; off < 512; off <<= 1) {
        int t = (threadIdx.x >= off) ? sh[threadIdx.x - off] : 0;
        __syncthreads();
        sh[threadIdx.x] += t;
        __syncthreads();
    }
    if (threadIdx.x < nb) g_bsum[threadIdx.x] = sh[threadIdx.x] - v;  // exclusive
}

// rowptr[i] = exclusive prefix; cursor[i] = rowptr[i]; dinv from degree
__global__ void k_scan3(int n, int e) {
    int i = blockIdx.x * blockDim.x + threadIdx.x;
    if (i < n) {
        int excl = g_tmp[i] - g_degi[i] + g_bsum[i / SCB];
        g_rowptr[i] = excl;
        g_cursor[i] = excl;
        g_dinv[i]   = rsqrtf((float)(g_degi[i] + 1));
    }
    if (i == 0) g_rowptr[n] = e;
}

__global__ void k_fill(const int* __restrict__ src,
                       const int* __restrict__ dst, int e) {
    int i = blockIdx.x * blockDim.x + threadIdx.x;
    if (i >= e) return;
    int d = dst[i];
    int pos = atomicAdd(&g_cursor[d], 1);
    g_csrc[pos] = src[i];
}

// ---------------------------------------------------------------------------
// per-warp row GEMM: A[row] = (X[row] @ W) * dinv[row]
__global__ void k_gemm_scale(const float* __restrict__ X,
                             const float* __restrict__ W,
                             int n) {
    __shared__ float Ws[HD * HD];
    for (int i = threadIdx.x; i < HD * HD; i += blockDim.x)
        Ws[i] = W[i];
    __syncthreads();

    int warp = threadIdx.x >> 5;
    int lane = threadIdx.x & 31;
    int row  = blockIdx.x * (blockDim.x >> 5) + warp;
    if (row >= n) return;

    float x0 = X[row * HD + lane];
    float x1 = X[row * HD + lane + 32];
    float a0 = 0.f, a1 = 0.f;
#pragma unroll
    for (int k = 0; k < HD; k++) {
        float xk = __shfl_sync(0xffffffffu, (k < 32) ? x0 : x1, k & 31);
        a0 = fmaf(xk, Ws[k * HD + lane], a0);
        a1 = fmaf(xk, Ws[k * HD + lane + 32], a1);
    }
    float s = g_dinv[row];
    float* A = (float*)g_A4;
    A[row * HD + lane]      = a0 * s;
    A[row * HD + lane + 32] = a1 * s;
}

// ---------------------------------------------------------------------------
// Gather core: 16 lanes per node, 4-way unrolled edge loop.
// 4 independent index loads (L1 broadcast across the group) then 4 independent
// LDG.128 row loads -> MLP~4 on the L2-latency chain, no shfl overhead.
__device__ __forceinline__ float4 gather_node(int node, int sub) {
    float4 acc = g_A4[node * 16 + sub];          // self-loop seed
    int beg = __ldg(&g_rowptr[node]);
    int end = __ldg(&g_rowptr[node + 1]);

    int j = beg;
    for (; j + 4 <= end; j += 4) {
        int s0 = __ldg(&g_csrc[j + 0]);
        int s1 = __ldg(&g_csrc[j + 1]);
        int s2 = __ldg(&g_csrc[j + 2]);
        int s3 = __ldg(&g_csrc[j + 3]);
        float4 v0 = __ldg(&g_A4[s0 * 16 + sub]);
        float4 v1 = __ldg(&g_A4[s1 * 16 + sub]);
        float4 v2 = __ldg(&g_A4[s2 * 16 + sub]);
        float4 v3 = __ldg(&g_A4[s3 * 16 + sub]);
        acc.x += v0.x + v1.x + v2.x + v3.x;
        acc.y += v0.y + v1.y + v2.y + v3.y;
        acc.z += v0.z + v1.z + v2.z + v3.z;
        acc.w += v0.w + v1.w + v2.w + v3.w;
    }
    for (; j < end; j++) {
        int s = __ldg(&g_csrc[j]);
        float4 v = __ldg(&g_A4[s * 16 + sub]);
        acc.x += v.x; acc.y += v.y; acc.z += v.z; acc.w += v.w;
    }
    return acc;
}

// gather layer 1: h1 = relu(dinv*(selfA + sum_nb A) + b) -> g_B4
__global__ void k_gather_store(const float* __restrict__ bias, int n) {
    int gid  = blockIdx.x * blockDim.x + threadIdx.x;
    int node = gid >> 4;
    int sub  = gid & 15;
    if (node >= n) return;

    float4 acc = gather_node(node, sub);
    float d = g_dinv[node];
    float4 b = __ldg(&((const float4*)bias)[sub]);
    acc.x = fmaxf(fmaf(acc.x, d, b.x), 0.f);
    acc.y = fmaxf(fmaf(acc.y, d, b.y), 0.f);
    acc.z = fmaxf(fmaf(acc.z, d, b.z), 0.f);
    acc.w = fmaxf(fmaf(acc.w, d, b.w), 0.f);
    g_B4[node * 16 + sub] = acc;
}

// gather layer 2 fused with pooling: h2 never hits memory
__global__ void k_gather_pool(const float* __restrict__ bias,
                              const int* __restrict__ batch, int n) {
    int gid  = blockIdx.x * blockDim.x + threadIdx.x;
    int node = gid >> 4;
    int sub  = gid & 15;
    if (node >= n) return;

    float4 acc = gather_node(node, sub);
    float d = g_dinv[node];
    float4 b = __ldg(&((const float4*)bias)[sub]);
    acc.x = fmaxf(fmaf(acc.x, d, b.x), 0.f);
    acc.y = fmaxf(fmaf(acc.y, d, b.y), 0.f);
    acc.z = fmaxf(fmaf(acc.z, d, b.z), 0.f);
    acc.w = fmaxf(fmaf(acc.w, d, b.w), 0.f);

    int g = __ldg(&batch[node]);
    float4* p = &g_S4[g * 16 + sub];
    asm volatile("red.global.add.v4.f32 [%0], {%1,%2,%3,%4};"
                 :: "l"(p), "f"(acc.x), "f"(acc.y), "f"(acc.z), "f"(acc.w)
                 : "memory");
    if (sub == 0) atomicAdd(&g_cnt[g], 1.0f);
}

// ---------------------------------------------------------------------------
__global__ void k_head(const float* __restrict__ Wfc,
                       const float* __restrict__ bfc,
                       float* __restrict__ out) {
    __shared__ float Wf[HD * OD];
    __shared__ float bf[OD];
    for (int i = threadIdx.x; i < HD * OD; i += blockDim.x) Wf[i] = Wfc[i];
    if (threadIdx.x < OD) bf[threadIdx.x] = bfc[threadIdx.x];
    __syncthreads();

    int g = blockIdx.x * blockDim.x + threadIdx.x;
    if (g >= GB) return;

    const float* sums = (const float*)g_S4;
    float inv = 1.0f / fmaxf(g_cnt[g], 1.0f);
    float logits[OD];
#pragma unroll
    for (int o = 0; o < OD; o++) logits[o] = bf[o];
#pragma unroll 8
    for (int h = 0; h < HD; h++) {
        float p = sums[g * HD + h] * inv;
#pragma unroll
        for (int o = 0; o < OD; o++)
            logits[o] = fmaf(p, Wf[h * OD + o], logits[o]);
    }
    float m = logits[0];
#pragma unroll
    for (int o = 1; o < OD; o++) m = fmaxf(m, logits[o]);
    float sum = 0.f;
#pragma unroll
    for (int o = 0; o < OD; o++) sum += __expf(logits[o] - m);
    float lse = __logf(sum);
#pragma unroll
    for (int o = 0; o < OD; o++) out[g * OD + o] = logits[o] - m - lse;
}

// ---------------------------------------------------------------------------
static float* s_dB = nullptr;

namespace {
struct ModulePreload {
    ModulePreload() {
        setenv("CUDA_MODULE_LOADING", "EAGER", 1);
        cudaFree(0);
        void* p = nullptr;
        cudaGetSymbolAddress(&p, g_B4);
        s_dB = (float*)p;
        cudaFuncAttributes a;
        cudaFuncGetAttributes(&a, (const void*)k_init);
        cudaFuncGetAttributes(&a, (const void*)k_hist);
        cudaFuncGetAttributes(&a, (const void*)k_scan1);
        cudaFuncGetAttributes(&a, (const void*)k_scan2);
        cudaFuncGetAttributes(&a, (const void*)k_scan3);
        cudaFuncGetAttributes(&a, (const void*)k_fill);
        cudaFuncGetAttributes(&a, (const void*)k_gemm_scale);
        cudaFuncGetAttributes(&a, (const void*)k_gather_store);
        cudaFuncGetAttributes(&a, (const void*)k_gather_pool);
        cudaFuncGetAttributes(&a, (const void*)k_head);
        k_init<<<1, 32>>>(0);
        k_hist<<<1, 32>>>((const int*)s_dB, 0);
        k_scan1<<<1, SCB>>>(0);
        k_scan2<<<1, 512>>>(0);
        k_scan3<<<1, 32>>>(0, 0);
        k_fill<<<1, 32>>>((const int*)s_dB, (const int*)s_dB, 0);
        k_gemm_scale<<<1, 256>>>(s_dB, s_dB, 0);
        k_gather_store<<<1, 32>>>(s_dB, 0);
        k_gather_pool<<<1, 32>>>(s_dB, (const int*)s_dB, 0);
        cudaDeviceSynchronize();   // host code outside kernel_launch: allowed
    }
};
static ModulePreload s_preload;
}

// ---------------------------------------------------------------------------
extern "C" void kernel_launch(void* const* d_in, const int* in_sizes, int n_in,
                              void* d_out, int out_size) {
    const float* x    = (const float*)d_in[0];
    const int*   ei   = (const int*)d_in[1];
    const int*   bat  = (const int*)d_in[2];
    const float* W1   = (const float*)d_in[3];
    const float* b1   = (const float*)d_in[4];
    const float* W2   = (const float*)d_in[5];
    const float* b2   = (const float*)d_in[6];
    const float* Wfc  = (const float*)d_in[7];
    const float* bfc  = (const float*)d_in[8];
    float*       out  = (float*)d_out;

    const int n = in_sizes[0] / HD;       // 80000
    const int e = in_sizes[1] / 2;        // 1280000
    const int* src = ei;
    const int* dst = ei + e;

    const int T = 256;
    int nB  = (n + T - 1) / T;
    int eB  = (e + T - 1) / T;
    int n16 = (n * 16 + T - 1) / T;
    int gemmB = (n + 7) / 8;

    // CSR build (by dst) + dinv
    k_init<<<nB, T>>>(n);
    k_hist<<<eB, T>>>(dst, e);
    k_scan1<<<(n + SCB - 1) / SCB, SCB>>>(n);
    k_scan2<<<1, 512>>>((n + SCB - 1) / SCB);
    k_scan3<<<nB, T>>>(n, e);
    k_fill<<<eB, T>>>(src, dst, e);

    // layer 1
    k_gemm_scale<<<gemmB, T>>>(x, W1, n);
    k_gather_store<<<n16, T>>>(b1, n);
    // layer 2 (+ fused pooling)
    k_gemm_scale<<<gemmB, T>>>(s_dB, W2, n);
    k_gather_pool<<<n16, T>>>(b2, bat, n);
    // head
    k_head<<<1, GB>>>(Wfc, bfc, out);
}

// round 11
// speedup vs baseline: 1.2557x; 1.0643x over previous
#include <cuda_runtime.h>
#include <cuda_bf16.h>
#include <stdint.h>
#include <stdlib.h>

#define NMAX 80000
#define EMAX 1280000
#define HD   64
#define OD   10
#define GB   512
#define SCB  256
#define NSB  ((NMAX + SCB - 1) / SCB)

// Scratch (module globals; eager-loaded in ctor)
__device__ int    g_degi[NMAX];
__device__ int    g_rowptr[NMAX + 1];
__device__ int    g_cursor[NMAX];
__device__ int    g_csrc[EMAX];
__device__ int    g_tmp[NMAX];
__device__ int    g_bsum[NSB + 1];
__device__ float  g_dinv[NMAX];
__device__ uint2  g_Abf[NMAX * 16];   // bf16 A rows: 64 cols = 32 uints = 16 uint2
__device__ float4 g_B4[NMAX * 16];    // h1 (fp32)
__device__ float4 g_S4[GB * 16];      // pooled sums
__device__ float  g_cnt[GB];

// ---------------------------------------------------------------------------
__global__ void k_init(int n) {
    int i = blockIdx.x * blockDim.x + threadIdx.x;
    if (i < n) g_degi[i] = 0;
    if (i < GB * 16) g_S4[i] = make_float4(0.f, 0.f, 0.f, 0.f);
    if (i < GB) g_cnt[i] = 0.0f;
}

__global__ void k_hist(const int* __restrict__ dst, int e) {
    int i = blockIdx.x * blockDim.x + threadIdx.x;
    if (i < e) atomicAdd(&g_degi[dst[i]], 1);
}

__global__ void k_scan1(int n) {
    __shared__ int sh[SCB];
    int i = blockIdx.x * SCB + threadIdx.x;
    int v = (i < n) ? g_degi[i] : 0;
    sh[threadIdx.x] = v;
    __syncthreads();
#pragma unroll
    for (int off = 1; off < SCB; off <<= 1) {
        int t = (threadIdx.x >= off) ? sh[threadIdx.x - off] : 0;
        __syncthreads();
        sh[threadIdx.x] += t;
        __syncthreads();
    }
    if (i < n) g_tmp[i] = sh[threadIdx.x];
    if (threadIdx.x == SCB - 1) g_bsum[blockIdx.x] = sh[SCB - 1];
}

__global__ void k_scan2(int nb) {
    __shared__ int sh[512];
    int v = (threadIdx.x < nb) ? g_bsum[threadIdx.x] : 0;
    sh[threadIdx.x] = v;
    __syncthreads();
#pragma unroll
    for (int off = 1; off < 512; off <<= 1) {
        int t = (threadIdx.x >= off) ? sh[threadIdx.x - off] : 0;
        __syncthreads();
        sh[threadIdx.x] += t;
        __syncthreads();
    }
    if (threadIdx.x < nb) g_bsum[threadIdx.x] = sh[threadIdx.x] - v;
}

__global__ void k_scan3(int n, int e) {
    int i = blockIdx.x * blockDim.x + threadIdx.x;
    if (i < n) {
        int excl = g_tmp[i] - g_degi[i] + g_bsum[i / SCB];
        g_rowptr[i] = excl;
        g_cursor[i] = excl;
        g_dinv[i]   = rsqrtf((float)(g_degi[i] + 1));
    }
    if (i == 0) g_rowptr[n] = e;
}

__global__ void k_fill(const int* __restrict__ src,
                       const int* __restrict__ dst, int e) {
    int i = blockIdx.x * blockDim.x + threadIdx.x;
    if (i >= e) return;
    int d = dst[i];
    int pos = atomicAdd(&g_cursor[d], 1);
    g_csrc[pos] = src[i];
}

// ---------------------------------------------------------------------------
// per-warp row GEMM -> bf16 rows. Lane computes cols {2l, 2l+1}.
// do_scale: multiply by dinv[row] in epilogue (layer 2 path).
__global__ void k_gemm_bf16(const float* __restrict__ X,
                            const float* __restrict__ W,
                            int n, int do_scale) {
    __shared__ float Ws[HD * HD];
    for (int i = threadIdx.x; i < HD * HD; i += blockDim.x)
        Ws[i] = W[i];
    __syncthreads();

    int warp = threadIdx.x >> 5;
    int lane = threadIdx.x & 31;
    int row  = blockIdx.x * (blockDim.x >> 5) + warp;
    if (row >= n) return;

    float x0 = X[row * HD + lane];
    float x1 = X[row * HD + lane + 32];
    const float2* W2 = (const float2*)Ws;
    float a0 = 0.f, a1 = 0.f;
#pragma unroll
    for (int k = 0; k < HD; k++) {
        float xk = __shfl_sync(0xffffffffu, (k < 32) ? x0 : x1, k & 31);
        float2 w = W2[k * 32 + lane];
        a0 = fmaf(xk, w.x, a0);
        a1 = fmaf(xk, w.y, a1);
    }
    if (do_scale) {
        float s = g_dinv[row];
        a0 *= s; a1 *= s;
    }
    __nv_bfloat162 h = __floats2bfloat162_rn(a0, a1);
    ((unsigned int*)g_Abf)[row * 32 + lane] = *(unsigned int*)&h;
}

// elementwise: A *= dinv[row] (in place, bf16) — joins GEMM1 with CSR branch
__global__ void k_scaleA(int n) {
    int i = blockIdx.x * blockDim.x + threadIdx.x;  // over n*32 uints
    if (i >= n * 32) return;
    unsigned int u = ((unsigned int*)g_Abf)[i];
    float s = g_dinv[i >> 5];
    float2 f = __bfloat1622float2(*(__nv_bfloat162*)&u);
    f.x *= s; f.y *= s;
    __nv_bfloat162 h = __floats2bfloat162_rn(f.x, f.y);
    ((unsigned int*)g_Abf)[i] = *(unsigned int*)&h;
}

// ---------------------------------------------------------------------------
// Gather core: 16 lanes/node, lane covers cols 4sub..4sub+3 (uint2 = 4 bf16).
// One 128B L2 line per edge row. fp32 accumulation.
__device__ __forceinline__ float4 gather_node(int node, int sub) {
    uint2 su = __ldg(&g_Abf[node * 16 + sub]);     // self (already dinv-scaled)
    float2 s0 = __bfloat1622float2(*(__nv_bfloat162*)&su.x);
    float2 s1 = __bfloat1622float2(*(__nv_bfloat162*)&su.y);
    float4 acc = make_float4(s0.x, s0.y, s1.x, s1.y);

    int beg = __ldg(&g_rowptr[node]);
    int end = __ldg(&g_rowptr[node + 1]);
    int j = beg;
    for (; j + 4 <= end; j += 4) {
        int i0 = __ldg(&g_csrc[j + 0]);
        int i1 = __ldg(&g_csrc[j + 1]);
        int i2 = __ldg(&g_csrc[j + 2]);
        int i3 = __ldg(&g_csrc[j + 3]);
        uint2 u0 = __ldg(&g_Abf[i0 * 16 + sub]);
        uint2 u1 = __ldg(&g_Abf[i1 * 16 + sub]);
        uint2 u2 = __ldg(&g_Abf[i2 * 16 + sub]);
        uint2 u3 = __ldg(&g_Abf[i3 * 16 + sub]);
        float2 a, b;
        a = __bfloat1622float2(*(__nv_bfloat162*)&u0.x); b = __bfloat1622float2(*(__nv_bfloat162*)&u0.y);
        acc.x += a.x; acc.y += a.y; acc.z += b.x; acc.w += b.y;
        a = __bfloat1622float2(*(__nv_bfloat162*)&u1.x); b = __bfloat1622float2(*(__nv_bfloat162*)&u1.y);
        acc.x += a.x; acc.y += a.y; acc.z += b.x; acc.w += b.y;
        a = __bfloat1622float2(*(__nv_bfloat162*)&u2.x); b = __bfloat1622float2(*(__nv_bfloat162*)&u2.y);
        acc.x += a.x; acc.y += a.y; acc.z += b.x; acc.w += b.y;
        a = __bfloat1622float2(*(__nv_bfloat162*)&u3.x); b = __bfloat1622float2(*(__nv_bfloat162*)&u3.y);
        acc.x += a.x; acc.y += a.y; acc.z += b.x; acc.w += b.y;
    }
    for (; j < end; j++) {
        int s = __ldg(&g_csrc[j]);
        uint2 u = __ldg(&g_Abf[s * 16 + sub]);
        float2 a = __bfloat1622float2(*(__nv_bfloat162*)&u.x);
        float2 b = __bfloat1622float2(*(__nv_bfloat162*)&u.y);
        acc.x += a.x; acc.y += a.y; acc.z += b.x; acc.w += b.y;
    }
    return acc;
}

// gather layer 1 -> h1 (fp32)
__global__ void k_gather_store(const float* __restrict__ bias, int n) {
    int gid  = blockIdx.x * blockDim.x + threadIdx.x;
    int node = gid >> 4;
    int sub  = gid & 15;
    if (node >= n) return;

    float4 acc = gather_node(node, sub);
    float d = g_dinv[node];
    float4 b = __ldg(&((const float4*)bias)[sub]);
    acc.x = fmaxf(fmaf(acc.x, d, b.x), 0.f);
    acc.y = fmaxf(fmaf(acc.y, d, b.y), 0.f);
    acc.z = fmaxf(fmaf(acc.z, d, b.z), 0.f);
    acc.w = fmaxf(fmaf(acc.w, d, b.w), 0.f);
    g_B4[node * 16 + sub] = acc;
}

// gather layer 2 fused with pooling
__global__ void k_gather_pool(const float* __restrict__ bias,
                              const int* __restrict__ batch, int n) {
    int gid  = blockIdx.x * blockDim.x + threadIdx.x;
    int node = gid >> 4;
    int sub  = gid & 15;
    if (node >= n) return;

    float4 acc = gather_node(node, sub);
    float d = g_dinv[node];
    float4 b = __ldg(&((const float4*)bias)[sub]);
    acc.x = fmaxf(fmaf(acc.x, d, b.x), 0.f);
    acc.y = fmaxf(fmaf(acc.y, d, b.y), 0.f);
    acc.z = fmaxf(fmaf(acc.z, d, b.z), 0.f);
    acc.w = fmaxf(fmaf(acc.w, d, b.w), 0.f);

    int g = __ldg(&batch[node]);
    float4* p = &g_S4[g * 16 + sub];
    asm volatile("red.global.add.v4.f32 [%0], {%1,%2,%3,%4};"
                 :: "l"(p), "f"(acc.x), "f"(acc.y), "f"(acc.z), "f"(acc.w)
                 : "memory");
    if (sub == 0) atomicAdd(&g_cnt[g], 1.0f);
}

// ---------------------------------------------------------------------------
__global__ void k_head(const float* __restrict__ Wfc,
                       const float* __restrict__ bfc,
                       float* __restrict__ out) {
    __shared__ float Wf[HD * OD];
    __shared__ float bf[OD];
    for (int i = threadIdx.x; i < HD * OD; i += blockDim.x) Wf[i] = Wfc[i];
    if (threadIdx.x < OD) bf[threadIdx.x] = bfc[threadIdx.x];
    __syncthreads();

    int g = blockIdx.x * blockDim.x + threadIdx.x;
    if (g >= GB) return;

    const float* sums = (const float*)g_S4;
    float inv = 1.0f / fmaxf(g_cnt[g], 1.0f);
    float logits[OD];
#pragma unroll
    for (int o = 0; o < OD; o++) logits[o] = bf[o];
#pragma unroll 8
    for (int h = 0; h < HD; h++) {
        float p = sums[g * HD + h] * inv;
#pragma unroll
        for (int o = 0; o < OD; o++)
            logits[o] = fmaf(p, Wf[h * OD + o], logits[o]);
    }
    float m = logits[0];
#pragma unroll
    for (int o = 1; o < OD; o++) m = fmaxf(m, logits[o]);
    float sum = 0.f;
#pragma unroll
    for (int o = 0; o < OD; o++) sum += __expf(logits[o] - m);
    float lse = __logf(sum);
#pragma unroll
    for (int o = 0; o < OD; o++) out[g * OD + o] = logits[o] - m - lse;
}

// ---------------------------------------------------------------------------
static float*       s_dB = nullptr;     // device addr of g_B4
static cudaStream_t s_s2 = nullptr;     // fork stream for GEMM1
static cudaEvent_t  s_evA = nullptr, s_evB = nullptr;

namespace {
struct ModulePreload {
    ModulePreload() {
        setenv("CUDA_MODULE_LOADING", "EAGER", 1);
        cudaFree(0);
        void* p = nullptr;
        cudaGetSymbolAddress(&p, g_B4);
        s_dB = (float*)p;
        cudaStreamCreateWithFlags(&s_s2, cudaStreamNonBlocking);
        cudaEventCreateWithFlags(&s_evA, cudaEventDisableTiming);
        cudaEventCreateWithFlags(&s_evB, cudaEventDisableTiming);
        cudaFuncAttributes a;
        cudaFuncGetAttributes(&a, (const void*)k_init);
        cudaFuncGetAttributes(&a, (const void*)k_hist);
        cudaFuncGetAttributes(&a, (const void*)k_scan1);
        cudaFuncGetAttributes(&a, (const void*)k_scan2);
        cudaFuncGetAttributes(&a, (const void*)k_scan3);
        cudaFuncGetAttributes(&a, (const void*)k_fill);
        cudaFuncGetAttributes(&a, (const void*)k_gemm_bf16);
        cudaFuncGetAttributes(&a, (const void*)k_scaleA);
        cudaFuncGetAttributes(&a, (const void*)k_gather_store);
        cudaFuncGetAttributes(&a, (const void*)k_gather_pool);
        cudaFuncGetAttributes(&a, (const void*)k_head);
        k_init<<<1, 32>>>(0);
        k_hist<<<1, 32>>>((const int*)s_dB, 0);
        k_scan1<<<1, SCB>>>(0);
        k_scan2<<<1, 512>>>(0);
        k_scan3<<<1, 32>>>(0, 0);
        k_fill<<<1, 32>>>((const int*)s_dB, (const int*)s_dB, 0);
        k_gemm_bf16<<<1, 256>>>(s_dB, s_dB, 0, 0);
        k_scaleA<<<1, 32>>>(0);
        k_gather_store<<<1, 32>>>(s_dB, 0);
        k_gather_pool<<<1, 32>>>(s_dB, (const int*)s_dB, 0);
        cudaDeviceSynchronize();   // host code outside kernel_launch: allowed
    }
};
static ModulePreload s_preload;
}

// ---------------------------------------------------------------------------
extern "C" void kernel_launch(void* const* d_in, const int* in_sizes, int n_in,
                              void* d_out, int out_size) {
    const float* x    = (const float*)d_in[0];
    const int*   ei   = (const int*)d_in[1];
    const int*   bat  = (const int*)d_in[2];
    const float* W1   = (const float*)d_in[3];
    const float* b1   = (const float*)d_in[4];
    const float* W2   = (const float*)d_in[5];
    const float* b2   = (const float*)d_in[6];
    const float* Wfc  = (const float*)d_in[7];
    const float* bfc  = (const float*)d_in[8];
    float*       out  = (float*)d_out;

    const int n = in_sizes[0] / HD;       // 80000
    const int e = in_sizes[1] / 2;        // 1280000
    const int* src = ei;
    const int* dst = ei + e;

    const int T = 256;
    int nB  = (n + T - 1) / T;
    int eB  = (e + T - 1) / T;
    int n16 = (n * 16 + T - 1) / T;
    int n32 = (n * 32 + T - 1) / T;
    int gemmB = (n + 7) / 8;

    // Fork: GEMM1 (no dinv dependency) on s2, concurrent with CSR build.
    cudaEventRecord(s_evA, 0);
    cudaStreamWaitEvent(s_s2, s_evA, 0);
    k_gemm_bf16<<<gemmB, T, 0, s_s2>>>(x, W1, n, 0);
    cudaEventRecord(s_evB, s_s2);

    // Main stream: CSR build (by dst) + dinv
    k_init<<<nB, T>>>(n);
    k_hist<<<eB, T>>>(dst, e);
    k_scan1<<<(n + SCB - 1) / SCB, SCB>>>(n);
    k_scan2<<<1, 512>>>((n + SCB - 1) / SCB);
    k_scan3<<<nB, T>>>(n, e);
    k_fill<<<eB, T>>>(src, dst, e);

    // Join, then apply dinv to A in place
    cudaStreamWaitEvent(0, s_evB, 0);
    k_scaleA<<<n32, T>>>(n);

    // layer 1
    k_gather_store<<<n16, T>>>(b1, n);
    // layer 2 (dinv folded into GEMM epilogue) + fused pooling
    k_gemm_bf16<<<gemmB, T>>>(s_dB, W2, n, 1);
    k_gather_pool<<<n16, T>>>(b2, bat, n);
    // head
    k_head<<<1, GB>>>(Wfc, bfc, out);
}

// round 12
// speedup vs baseline: 1.4609x; 1.1634x over previous
#include <cuda_runtime.h>
#include <cuda_bf16.h>
#include <stdint.h>
#include <stdlib.h>

#define NMAX 80000
#define EMAX 1280000
#define HD   64
#define OD   10
#define GB   512
#define SCB  256
#define NSB  ((NMAX + SCB - 1) / SCB)

// Scratch (module globals; eager-loaded in ctor)
__device__ int    g_degi[NMAX];
__device__ int    g_rowptr[NMAX + 1];
__device__ int    g_cursor[NMAX];
__device__ int    g_csrc[EMAX];
__device__ int    g_tmp[NMAX];
__device__ int    g_bsum[NSB + 1];
__device__ float  g_dinv[NMAX];
__device__ uint2  g_Abf[NMAX * 16];    // layer-1 messages A1 (bf16, dinv-scaled)
__device__ uint2  g_A2bf[NMAX * 16];   // layer-2 messages A2 (bf16, dinv-scaled)
__device__ float4 g_S4[GB * 16];       // pooled sums
__device__ float  g_cnt[GB];

// ---------------------------------------------------------------------------
__global__ void k_init(int n) {
    int i = blockIdx.x * blockDim.x + threadIdx.x;
    if (i < n) g_degi[i] = 0;
    if (i < GB * 16) g_S4[i] = make_float4(0.f, 0.f, 0.f, 0.f);
    if (i < GB) g_cnt[i] = 0.0f;
}

__global__ void k_hist(const int* __restrict__ dst, int e) {
    int i = blockIdx.x * blockDim.x + threadIdx.x;
    if (i < e) atomicAdd(&g_degi[dst[i]], 1);
}

__global__ void k_scan1(int n) {
    __shared__ int sh[SCB];
    int i = blockIdx.x * SCB + threadIdx.x;
    int v = (i < n) ? g_degi[i] : 0;
    sh[threadIdx.x] = v;
    __syncthreads();
#pragma unroll
    for (int off = 1; off < SCB; off <<= 1) {
        int t = (threadIdx.x >= off) ? sh[threadIdx.x - off] : 0;
        __syncthreads();
        sh[threadIdx.x] += t;
        __syncthreads();
    }
    if (i < n) g_tmp[i] = sh[threadIdx.x];
    if (threadIdx.x == SCB - 1) g_bsum[blockIdx.x] = sh[SCB - 1];
}

__global__ void k_scan2(int nb) {
    __shared__ int sh[512];
    int v = (threadIdx.x < nb) ? g_bsum[threadIdx.x] : 0;
    sh[threadIdx.x] = v;
    __syncthreads();
#pragma unroll
    for (int off = 1; off < 512; off <<= 1) {
        int t = (threadIdx.x >= off) ? sh[threadIdx.x - off] : 0;
        __syncthreads();
        sh[threadIdx.x] += t;
        __syncthreads();
    }
    if (threadIdx.x < nb) g_bsum[threadIdx.x] = sh[threadIdx.x] - v;
}

__global__ void k_scan3(int n, int e) {
    int i = blockIdx.x * blockDim.x + threadIdx.x;
    if (i < n) {
        int excl = g_tmp[i] - g_degi[i] + g_bsum[i / SCB];
        g_rowptr[i] = excl;
        g_cursor[i] = excl;
        g_dinv[i]   = rsqrtf((float)(g_degi[i] + 1));
    }
    if (i == 0) g_rowptr[n] = e;
}

__global__ void k_fill(const int* __restrict__ src,
                       const int* __restrict__ dst, int e) {
    int i = blockIdx.x * blockDim.x + threadIdx.x;
    if (i >= e) return;
    int d = dst[i];
    int pos = atomicAdd(&g_cursor[d], 1);
    g_csrc[pos] = src[i];
}

// ---------------------------------------------------------------------------
// per-warp row GEMM -> bf16 rows into g_Abf, epilogue applies dinv[row].
// (launched after scan3 so dinv is valid)
__global__ void k_gemm_bf16(const float* __restrict__ X,
                            const float* __restrict__ W, int n) {
    __shared__ float Ws[HD * HD];
    for (int i = threadIdx.x; i < HD * HD; i += blockDim.x)
        Ws[i] = W[i];
    __syncthreads();

    int warp = threadIdx.x >> 5;
    int lane = threadIdx.x & 31;
    int row  = blockIdx.x * (blockDim.x >> 5) + warp;
    if (row >= n) return;

    float x0 = X[row * HD + lane];
    float x1 = X[row * HD + lane + 32];
    const float2* W2 = (const float2*)Ws;
    float a0 = 0.f, a1 = 0.f;
#pragma unroll
    for (int k = 0; k < HD; k++) {
        float xk = __shfl_sync(0xffffffffu, (k < 32) ? x0 : x1, k & 31);
        float2 w = W2[k * 32 + lane];
        a0 = fmaf(xk, w.x, a0);
        a1 = fmaf(xk, w.y, a1);
    }
    float s = g_dinv[row];
    a0 *= s; a1 *= s;
    __nv_bfloat162 h = __floats2bfloat162_rn(a0, a1);
    ((unsigned int*)g_Abf)[row * 32 + lane] = *(unsigned int*)&h;
}

// ---------------------------------------------------------------------------
// Gather core over msg buffer: 16 lanes/node, lane covers 4 cols (uint2).
__device__ __forceinline__ float4 gather_node(const uint2* __restrict__ M,
                                              int node, int sub) {
    uint2 su = __ldg(&M[node * 16 + sub]);     // self-loop (pre-scaled)
    float2 s0 = __bfloat1622float2(*(__nv_bfloat162*)&su.x);
    float2 s1 = __bfloat1622float2(*(__nv_bfloat162*)&su.y);
    float4 acc = make_float4(s0.x, s0.y, s1.x, s1.y);

    int beg = __ldg(&g_rowptr[node]);
    int end = __ldg(&g_rowptr[node + 1]);
    int j = beg;
    for (; j + 4 <= end; j += 4) {
        int i0 = __ldg(&g_csrc[j + 0]);
        int i1 = __ldg(&g_csrc[j + 1]);
        int i2 = __ldg(&g_csrc[j + 2]);
        int i3 = __ldg(&g_csrc[j + 3]);
        uint2 u0 = __ldg(&M[i0 * 16 + sub]);
        uint2 u1 = __ldg(&M[i1 * 16 + sub]);
        uint2 u2 = __ldg(&M[i2 * 16 + sub]);
        uint2 u3 = __ldg(&M[i3 * 16 + sub]);
        float2 a, b;
        a = __bfloat1622float2(*(__nv_bfloat162*)&u0.x); b = __bfloat1622float2(*(__nv_bfloat162*)&u0.y);
        acc.x += a.x; acc.y += a.y; acc.z += b.x; acc.w += b.y;
        a = __bfloat1622float2(*(__nv_bfloat162*)&u1.x); b = __bfloat1622float2(*(__nv_bfloat162*)&u1.y);
        acc.x += a.x; acc.y += a.y; acc.z += b.x; acc.w += b.y;
        a = __bfloat1622float2(*(__nv_bfloat162*)&u2.x); b = __bfloat1622float2(*(__nv_bfloat162*)&u2.y);
        acc.x += a.x; acc.y += a.y; acc.z += b.x; acc.w += b.y;
        a = __bfloat1622float2(*(__nv_bfloat162*)&u3.x); b = __bfloat1622float2(*(__nv_bfloat162*)&u3.y);
        acc.x += a.x; acc.y += a.y; acc.z += b.x; acc.w += b.y;
    }
    for (; j < end; j++) {
        int s = __ldg(&g_csrc[j]);
        uint2 u = __ldg(&M[s * 16 + sub]);
        float2 a = __bfloat1622float2(*(__nv_bfloat162*)&u.x);
        float2 b = __bfloat1622float2(*(__nv_bfloat162*)&u.y);
        acc.x += a.x; acc.y += a.y; acc.z += b.x; acc.w += b.y;
    }
    return acc;
}

// ---------------------------------------------------------------------------
// FUSED: gather layer 1 -> h1 (registers) -> GEMM2 via shfl -> A2 (bf16)
// h1[node] lives in the node's 16-lane group (4 floats/lane), so the 64x64
// GEMM runs in-register: k-loop broadcasts h1[k] from owner lane (width=16).
__global__ void k_gather_gemm(const float* __restrict__ bias1,
                              const float* __restrict__ W2mat, int n) {
    __shared__ float4 Ws[HD * 16];            // W2[k][4c] as float4
    const float4* W4 = (const float4*)W2mat;
    for (int i = threadIdx.x; i < HD * 16; i += blockDim.x) Ws[i] = W4[i];
    __syncthreads();

    int gid  = blockIdx.x * blockDim.x + threadIdx.x;
    int node = gid >> 4;
    int sub  = gid & 15;
    bool valid = node < n;
    if (!valid) node = 0;                     // keep warp converged for shfl

    float4 acc = gather_node(g_Abf, node, sub);
    float d = g_dinv[node];
    float4 b = __ldg(&((const float4*)bias1)[sub]);
    float4 h;
    h.x = fmaxf(fmaf(acc.x, d, b.x), 0.f);
    h.y = fmaxf(fmaf(acc.y, d, b.y), 0.f);
    h.z = fmaxf(fmaf(acc.z, d, b.z), 0.f);
    h.w = fmaxf(fmaf(acc.w, d, b.w), 0.f);

    float4 o = make_float4(0.f, 0.f, 0.f, 0.f);
#pragma unroll
    for (int k = 0; k < HD; k++) {
        float hv = ((k & 3) == 0) ? h.x : ((k & 3) == 1) ? h.y
                 : ((k & 3) == 2) ? h.z : h.w;
        float hk = __shfl_sync(0xffffffffu, hv, k >> 2, 16);
        float4 w = Ws[k * 16 + sub];
        o.x = fmaf(hk, w.x, o.x);
        o.y = fmaf(hk, w.y, o.y);
        o.z = fmaf(hk, w.z, o.z);
        o.w = fmaf(hk, w.w, o.w);
    }
    if (valid) {
        o.x *= d; o.y *= d; o.z *= d; o.w *= d;      // pre-scale for layer 2
        __nv_bfloat162 p0 = __floats2bfloat162_rn(o.x, o.y);
        __nv_bfloat162 p1 = __floats2bfloat162_rn(o.z, o.w);
        uint2 u;
        u.x = *(unsigned int*)&p0;
        u.y = *(unsigned int*)&p1;
        g_A2bf[node * 16 + sub] = u;
    }
}

// gather layer 2 fused with pooling: h2 never hits memory
__global__ void k_gather_pool(const float* __restrict__ bias,
                              const int* __restrict__ batch, int n) {
    int gid  = blockIdx.x * blockDim.x + threadIdx.x;
    int node = gid >> 4;
    int sub  = gid & 15;
    if (node >= n) return;

    float4 acc = gather_node(g_A2bf, node, sub);
    float d = g_dinv[node];
    float4 b = __ldg(&((const float4*)bias)[sub]);
    acc.x = fmaxf(fmaf(acc.x, d, b.x), 0.f);
    acc.y = fmaxf(fmaf(acc.y, d, b.y), 0.f);
    acc.z = fmaxf(fmaf(acc.z, d, b.z), 0.f);
    acc.w = fmaxf(fmaf(acc.w, d, b.w), 0.f);

    int g = __ldg(&batch[node]);
    float4* p = &g_S4[g * 16 + sub];
    asm volatile("red.global.add.v4.f32 [%0], {%1,%2,%3,%4};"
                 :: "l"(p), "f"(acc.x), "f"(acc.y), "f"(acc.z), "f"(acc.w)
                 : "memory");
    if (sub == 0) atomicAdd(&g_cnt[g], 1.0f);
}

// ---------------------------------------------------------------------------
__global__ void k_head(const float* __restrict__ Wfc,
                       const float* __restrict__ bfc,
                       float* __restrict__ out) {
    __shared__ float Wf[HD * OD];
    __shared__ float bf[OD];
    for (int i = threadIdx.x; i < HD * OD; i += blockDim.x) Wf[i] = Wfc[i];
    if (threadIdx.x < OD) bf[threadIdx.x] = bfc[threadIdx.x];
    __syncthreads();

    int g = blockIdx.x * blockDim.x + threadIdx.x;
    if (g >= GB) return;

    const float* sums = (const float*)g_S4;
    float inv = 1.0f / fmaxf(g_cnt[g], 1.0f);
    float logits[OD];
#pragma unroll
    for (int o = 0; o < OD; o++) logits[o] = bf[o];
#pragma unroll 8
    for (int h = 0; h < HD; h++) {
        float p = sums[g * HD + h] * inv;
#pragma unroll
        for (int o = 0; o < OD; o++)
            logits[o] = fmaf(p, Wf[h * OD + o], logits[o]);
    }
    float m = logits[0];
#pragma unroll
    for (int o = 1; o < OD; o++) m = fmaxf(m, logits[o]);
    float sum = 0.f;
#pragma unroll
    for (int o = 0; o < OD; o++) sum += __expf(logits[o] - m);
    float lse = __logf(sum);
#pragma unroll
    for (int o = 0; o < OD; o++) out[g * OD + o] = logits[o] - m - lse;
}

// ---------------------------------------------------------------------------
static float*       s_dB = nullptr;
static cudaStream_t s_s2 = nullptr;
static cudaEvent_t  s_evA = nullptr, s_evB = nullptr;

namespace {
struct ModulePreload {
    ModulePreload() {
        setenv("CUDA_MODULE_LOADING", "EAGER", 1);
        cudaFree(0);
        void* p = nullptr;
        cudaGetSymbolAddress(&p, g_S4);
        s_dB = (float*)p;
        cudaStreamCreateWithFlags(&s_s2, cudaStreamNonBlocking);
        cudaEventCreateWithFlags(&s_evA, cudaEventDisableTiming);
        cudaEventCreateWithFlags(&s_evB, cudaEventDisableTiming);
        cudaFuncAttributes a;
        cudaFuncGetAttributes(&a, (const void*)k_init);
        cudaFuncGetAttributes(&a, (const void*)k_hist);
        cudaFuncGetAttributes(&a, (const void*)k_scan1);
        cudaFuncGetAttributes(&a, (const void*)k_scan2);
        cudaFuncGetAttributes(&a, (const void*)k_scan3);
        cudaFuncGetAttributes(&a, (const void*)k_fill);
        cudaFuncGetAttributes(&a, (const void*)k_gemm_bf16);
        cudaFuncGetAttributes(&a, (const void*)k_gather_gemm);
        cudaFuncGetAttributes(&a, (const void*)k_gather_pool);
        cudaFuncGetAttributes(&a, (const void*)k_head);
        k_init<<<1, 32>>>(0);
        k_hist<<<1, 32>>>((const int*)s_dB, 0);
        k_scan1<<<1, SCB>>>(0);
        k_scan2<<<1, 512>>>(0);
        k_scan3<<<1, 32>>>(0, 0);
        k_fill<<<1, 32>>>((const int*)s_dB, (const int*)s_dB, 0);
        k_gemm_bf16<<<1, 256>>>(s_dB, s_dB, 0);
        k_gather_gemm<<<1, 256>>>(s_dB, s_dB, 0);
        k_gather_pool<<<1, 32>>>(s_dB, (const int*)s_dB, 0);
        cudaDeviceSynchronize();   // host code outside kernel_launch: allowed
    }
};
static ModulePreload s_preload;
}

// ---------------------------------------------------------------------------
extern "C" void kernel_launch(void* const* d_in, const int* in_sizes, int n_in,
                              void* d_out, int out_size) {
    const float* x    = (const float*)d_in[0];
    const int*   ei   = (const int*)d_in[1];
    const int*   bat  = (const int*)d_in[2];
    const float* W1   = (const float*)d_in[3];
    const float* b1   = (const float*)d_in[4];
    const float* W2   = (const float*)d_in[5];
    const float* b2   = (const float*)d_in[6];
    const float* Wfc  = (const float*)d_in[7];
    const float* bfc  = (const float*)d_in[8];
    float*       out  = (float*)d_out;

    const int n = in_sizes[0] / HD;       // 80000
    const int e = in_sizes[1] / 2;        // 1280000
    const int* src = ei;
    const int* dst = ei + e;

    const int T = 256;
    int nB  = (n + T - 1) / T;
    int eB  = (e + T - 1) / T;
    int n16 = (n * 16 + T - 1) / T;
    int gemmB = (n + 7) / 8;

    // CSR build (by dst) + dinv
    k_init<<<nB, T>>>(n);
    k_hist<<<eB, T>>>(dst, e);
    k_scan1<<<(n + SCB - 1) / SCB, SCB>>>(n);
    k_scan2<<<1, 512>>>((n + SCB - 1) / SCB);
    k_scan3<<<nB, T>>>(n, e);

    // Fork: GEMM1 (needs dinv from scan3) overlaps with fill.
    cudaEventRecord(s_evA, 0);
    cudaStreamWaitEvent(s_s2, s_evA, 0);
    k_gemm_bf16<<<gemmB, T, 0, s_s2>>>(x, W1, n);
    cudaEventRecord(s_evB, s_s2);

    k_fill<<<eB, T>>>(src, dst, e);
    cudaStreamWaitEvent(0, s_evB, 0);     // join

    // layer 1 gather + fused GEMM2 -> A2 (bf16)
    k_gather_gemm<<<n16, T>>>(b1, W2, n);
    // layer 2 gather + fused pooling
    k_gather_pool<<<n16, T>>>(b2, bat, n);
    // head
    k_head<<<1, GB>>>(Wfc, bfc, out);
}